// round 15
// baseline (speedup 1.0000x reference)
#include <cuda_runtime.h>
#include <cuda_fp16.h>
#include <cstdint>
#include <cstddef>

#define N_NODES 50000
#define DIN 128
#define DHID 256
#define E_MAX 1000000
#define SCAN_NB ((N_NODES + 255) / 256)   // 196

// ---- scratch (static device globals; no allocation allowed) ----
__device__ int g_degi[N_NODES];
__device__ int g_off[N_NODES + 1];
__device__ int g_cur[N_NODES];
__device__ int g_esrc[E_MAX];
__device__ int g_psum[256];
__device__ uint16_t g_x16[N_NODES * DIN];      // x in fp16
__device__ uint16_t g_mean[N_NODES * DIN];     // layer1 neighbor mean, fp16
__device__ uint16_t g_h16[N_NODES * DHID];     // relu(h) fp16
__device__ uint16_t g_p16[N_NODES * DIN];      // p = h@W2l^T fp16
__device__ float    g_q[N_NODES * DIN];        // q = h@W2r^T fp32
__device__ uint16_t g_wh[2 * DHID * DHID];     // weights fp16

// ---------------------------------------------------------------------------
__device__ __forceinline__ uint32_t smem_u32(const void* p) {
    uint32_t a;
    asm("{ .reg .u64 t; cvta.to.shared.u64 t, %1; cvt.u32.u64 %0, t; }" : "=r"(a) : "l"(p));
    return a;
}
__device__ __forceinline__ uint32_t pack_f16(float x, float y) {
    __half2 t = __floats2half2_rn(x, y);
    return *reinterpret_cast<uint32_t*>(&t);
}
__device__ __forceinline__ void cpa16(uint32_t saddr, const void* g, int sz) {
    asm volatile("cp.async.cg.shared.global [%0], [%1], 16, %2;" :: "r"(saddr), "l"(g), "r"(sz));
}
__device__ __forceinline__ void mma_f16(float* c, const uint32_t* a, const uint32_t* b) {
    asm volatile(
        "mma.sync.aligned.m16n8k16.row.col.f32.f16.f16.f32 "
        "{%0,%1,%2,%3}, {%4,%5,%6,%7}, {%8,%9}, {%0,%1,%2,%3};"
        : "+f"(c[0]), "+f"(c[1]), "+f"(c[2]), "+f"(c[3])
        : "r"(a[0]), "r"(a[1]), "r"(a[2]), "r"(a[3]), "r"(b[0]), "r"(b[1]));
}
__device__ __forceinline__ void ldsm4(uint32_t* r, uint32_t a) {
    asm volatile("ldmatrix.sync.aligned.m8n8.x4.shared.b16 {%0,%1,%2,%3}, [%4];"
                 : "=r"(r[0]), "=r"(r[1]), "=r"(r[2]), "=r"(r[3]) : "r"(a));
}
__device__ __forceinline__ void acc_u2(float4& a, uint2 u) {
    float2 lo = __half22float2(*reinterpret_cast<__half2*>(&u.x));
    float2 hi = __half22float2(*reinterpret_cast<__half2*>(&u.y));
    a.x += lo.x; a.y += lo.y; a.z += hi.x; a.w += hi.y;
}

// ---------------------------------------------------------------------------
// CSR build
// ---------------------------------------------------------------------------
__global__ void zero_int_kernel(int* __restrict__ p, int n) {
    int i = blockIdx.x * blockDim.x + threadIdx.x;
    if (i < n) p[i] = 0;
}
__global__ void degi_kernel(const int* __restrict__ dst, int E, int* __restrict__ degi) {
    int i = blockIdx.x * blockDim.x + threadIdx.x;
    if (i < E) atomicAdd(&degi[dst[i]], 1);
}

// --- 3-phase device-wide exclusive scan of degi -> off ---
__global__ void scan1_kernel(const int* __restrict__ degi, int* __restrict__ psum) {
    __shared__ int sh[256];
    int i = blockIdx.x * 256 + threadIdx.x;
    sh[threadIdx.x] = (i < N_NODES) ? degi[i] : 0;
    __syncthreads();
#pragma unroll
    for (int o = 128; o > 0; o >>= 1) {
        if (threadIdx.x < o) sh[threadIdx.x] += sh[threadIdx.x + o];
        __syncthreads();
    }
    if (threadIdx.x == 0) psum[blockIdx.x] = sh[0];
}
__global__ void scan2_kernel(int* __restrict__ psum) {
    __shared__ int sh[256];
    int t = threadIdx.x;
    sh[t] = (t < SCAN_NB) ? psum[t] : 0;
    __syncthreads();
#pragma unroll
    for (int o = 1; o < 256; o <<= 1) {
        int u = (t >= o) ? sh[t - o] : 0;
        __syncthreads();
        sh[t] += u;
        __syncthreads();
    }
    if (t < SCAN_NB) psum[t] = (t == 0) ? 0 : sh[t - 1];
}
__global__ void scan3_kernel(const int* __restrict__ degi, const int* __restrict__ psum,
                             int* __restrict__ off, int* __restrict__ cur, int E) {
    const int t = threadIdx.x, b = blockIdx.x;
    const int i = b * 256 + t;
    const int lane = t & 31, w = t >> 5;
    int v = (i < N_NODES) ? degi[i] : 0;
    int s = v;
#pragma unroll
    for (int o = 1; o < 32; o <<= 1) {
        int u = __shfl_up_sync(0xffffffffu, s, o);
        if (lane >= o) s += u;
    }
    __shared__ int wsum[8];
    if (lane == 31) wsum[w] = s;
    __syncthreads();
    if (t < 8) {
        int ws = wsum[t];
#pragma unroll
        for (int o = 1; o < 8; o <<= 1) {
            int u = __shfl_up_sync(0xffu, ws, o);
            if (t >= o) ws += u;
        }
        wsum[t] = ws;
    }
    __syncthreads();
    int base = __ldg(psum + b) + ((w > 0) ? wsum[w - 1] : 0);
    if (i < N_NODES) {
        off[i] = base + s - v;   // exclusive
        cur[i] = 0;
    }
    if (i == 0) off[N_NODES] = E;
}

__global__ void fill_kernel(const int* __restrict__ src, const int* __restrict__ dst,
                            const int* __restrict__ off, int* __restrict__ cur,
                            int* __restrict__ esrc, int E) {
    int e = blockIdx.x * blockDim.x + threadIdx.x;
    if (e >= E) return;
    int d = dst[e];
    int p = atomicAdd(&cur[d], 1);
    esrc[off[d] + p] = src[e];
}

// ---------------------------------------------------------------------------
// fused convert: x -> fp16 (all threads) ; weights -> fp16 (first 32768 threads)
// ---------------------------------------------------------------------------
__global__ void conv_kernel(const float* __restrict__ x, uint16_t* __restrict__ x16,
                            const float* __restrict__ W1l, const float* __restrict__ W1r,
                            const float* __restrict__ W2l, const float* __restrict__ W2r,
                            uint16_t* __restrict__ wh) {
    int t = blockIdx.x * blockDim.x + threadIdx.x;
    if (t < N_NODES * DIN / 4) {
        float4 v = *reinterpret_cast<const float4*>(x + (size_t)t * 4);
        uint2 o;
        o.x = pack_f16(v.x, v.y);
        o.y = pack_f16(v.z, v.w);
        reinterpret_cast<uint2*>(x16)[t] = o;
    }
    if (t < 2 * DHID * DHID / 4) {
        int layer = t >> 14;
        int e0 = (t & 16383) * 4;
        int j = e0 >> 8, k = e0 & 255;
        float4 v;
        if (layer == 0) {
            v = (k < DIN) ? *reinterpret_cast<const float4*>(W1l + (size_t)j * DIN + k)
                          : *reinterpret_cast<const float4*>(W1r + (size_t)j * DIN + (k - DIN));
        } else {
            v = (j < 128) ? *reinterpret_cast<const float4*>(W2l + (size_t)j * DHID + k)
                          : *reinterpret_cast<const float4*>(W2r + (size_t)(j - 128) * DHID + k);
        }
        size_t o = (size_t)layer * DHID * DHID + e0;
        *reinterpret_cast<uint32_t*>(wh + o)     = pack_f16(v.x, v.y);
        *reinterpret_cast<uint32_t*>(wh + o + 2) = pack_f16(v.z, v.w);
    }
}

// ---------------------------------------------------------------------------
// CSR aggregation over fp16 features, one warp per node, 4-edge unroll.
// MODE 0: feat16 = x16. epilogue: mean -> g_mean (fp16, ld 128)
// MODE 1: feat16 = p16. epilogue: out = mean + q + b2 (fp32)
// ---------------------------------------------------------------------------
template <int MODE>
__global__ __launch_bounds__(256)
void agg_csr_kernel(const uint16_t* __restrict__ feat16,
                    const int* __restrict__ off, const int* __restrict__ esrc,
                    uint16_t* __restrict__ am,
                    const float* __restrict__ q, const float* __restrict__ b2,
                    float* __restrict__ out) {
    const int d = blockIdx.x * 8 + (threadIdx.x >> 5);
    if (d >= N_NODES) return;
    const int lane = threadIdx.x & 31;
    const uint2* F = reinterpret_cast<const uint2*>(feat16);

    const int beg = __ldg(off + d);
    const int end = __ldg(off + d + 1);

    float4 a0 = make_float4(0.f, 0.f, 0.f, 0.f), a1v = a0, a2 = a0, a3 = a0;
    int i = beg;
    for (; i + 4 <= end; i += 4) {
        int s0 = __ldg(esrc + i), s1 = __ldg(esrc + i + 1);
        int s2 = __ldg(esrc + i + 2), s3 = __ldg(esrc + i + 3);
        uint2 u0 = __ldg(F + (size_t)s0 * 32 + lane);
        uint2 u1 = __ldg(F + (size_t)s1 * 32 + lane);
        uint2 u2 = __ldg(F + (size_t)s2 * 32 + lane);
        uint2 u3 = __ldg(F + (size_t)s3 * 32 + lane);
        acc_u2(a0, u0); acc_u2(a1v, u1); acc_u2(a2, u2); acc_u2(a3, u3);
    }
    for (; i < end; i++) {
        int s = __ldg(esrc + i);
        uint2 u = __ldg(F + (size_t)s * 32 + lane);
        acc_u2(a0, u);
    }
    float4 acc;
    acc.x = (a0.x + a1v.x) + (a2.x + a3.x);
    acc.y = (a0.y + a1v.y) + (a2.y + a3.y);
    acc.z = (a0.z + a1v.z) + (a2.z + a3.z);
    acc.w = (a0.w + a1v.w) + (a2.w + a3.w);

    const float rd = 1.0f / (float)max(end - beg, 1);
    acc.x *= rd; acc.y *= rd; acc.z *= rd; acc.w *= rd;

    if (MODE == 0) {
        uint2 o;
        o.x = pack_f16(acc.x, acc.y);
        o.y = pack_f16(acc.z, acc.w);
        reinterpret_cast<uint2*>(am + (size_t)d * DIN)[lane] = o;
    } else {
        float4 qv = __ldg(reinterpret_cast<const float4*>(q) + (size_t)d * 32 + lane);
        float4 bb = __ldg(reinterpret_cast<const float4*>(b2) + lane);
        float4 o;
        o.x = acc.x + qv.x + bb.x;
        o.y = acc.y + qv.y + bb.y;
        o.z = acc.z + qv.z + bb.z;
        o.w = acc.w + qv.w + bb.w;
        reinterpret_cast<float4*>(out)[(size_t)d * 32 + lane] = o;
    }
}

// ---------------------------------------------------------------------------
// fp16 GEMM: C = A @ B^T, 256x128 tile, 512 threads.
// B fully prefetched at entry (8 chunks, resident); A double-buffered.
// MODE 0: A(row,k) = k<128 ? mean[row,k] : x16[row,k-128]. relu(+bias) -> fp16 (ld 256)
// MODE 1: A = h16 (ld 256). split: col0==0 -> p16 (ld 128); col0==128 -> fp32 q (ld 128)
// ---------------------------------------------------------------------------
#define LDA 40
#define ST_A (256 * LDA)                 // 10240 elems per A stage
#define ST_B (128 * LDA)                 // 5120 elems per B chunk
#define OFF_B (2 * ST_A)                 // B after 2 A stages
#define SMEM_ELEMS (2 * ST_A + 8 * ST_B) // 61440 elems = 122880 B

template <int MODE>
__global__ __launch_bounds__(512, 1)
void gemm_mma(const uint16_t* __restrict__ Am, const uint16_t* __restrict__ Ax,
              const uint16_t* __restrict__ Bh,
              const float* __restrict__ bias,
              uint16_t* __restrict__ Ch, float* __restrict__ Cq) {
    extern __shared__ __align__(16) uint16_t smem[];
    const uint32_t sb = smem_u32(smem);

    const int tid  = threadIdx.x;
    const int wid  = tid >> 5;
    const int lane = tid & 31;
    const int g    = lane >> 2;
    const int tg   = lane & 3;
    const int row0 = blockIdx.x * 256;
    const int col0 = blockIdx.y * 128;
    const int wm   = wid >> 2;
    const int wn   = wid & 3;

    const int qa0 = tid * 2;
    const int ar0 = qa0 >> 2, as0 = (qa0 & 3) * 8;
    const int ar1 = (qa0 + 1) >> 2, as1 = ((qa0 + 1) & 3) * 8;
    const int br = tid >> 2, bs = (tid & 3) * 8;

    const int aTerm = (lane & 15) * LDA + (lane >> 4) * 8;
    const int bTerm = ((lane & 7) + ((lane >> 4) << 3)) * LDA + ((lane >> 3) & 1) * 8;
    const int aTileOff = (wm * 64) * LDA;
    const int bTileOff = (wn * 32) * LDA;

    float acc[4][4][4];
#pragma unroll
    for (int i = 0; i < 4; i++)
#pragma unroll
        for (int j = 0; j < 4; j++)
#pragma unroll
            for (int k = 0; k < 4; k++) acc[i][j][k] = 0.f;

    auto load_A = [&](int kt, int s) {
        const int k0 = kt * 32;
        const uint32_t sbase = sb + (uint32_t)(s * ST_A) * 2;
        int r0a = row0 + ar0, r1a = row0 + ar1;
        int sz0 = (r0a < N_NODES) ? 16 : 0;
        int sz1 = (r1a < N_NODES) ? 16 : 0;
        if (MODE == 0) {
            const uint16_t* base = (k0 < DIN) ? Am : Ax;
            int kh = k0 & (DIN - 1);
            size_t o0 = (size_t)min(r0a, N_NODES - 1) * DIN + kh + as0;
            size_t o1 = (size_t)min(r1a, N_NODES - 1) * DIN + kh + as1;
            cpa16(sbase + (ar0 * LDA + as0) * 2, base + o0, sz0);
            cpa16(sbase + (ar1 * LDA + as1) * 2, base + o1, sz1);
        } else {
            size_t o0 = (size_t)min(r0a, N_NODES - 1) * DHID + k0 + as0;
            size_t o1 = (size_t)min(r1a, N_NODES - 1) * DHID + k0 + as1;
            cpa16(sbase + (ar0 * LDA + as0) * 2, Am + o0, sz0);
            cpa16(sbase + (ar1 * LDA + as1) * 2, Am + o1, sz1);
        }
    };

    // ---- entry: prefetch ALL of B (8 chunks) + A stage 0, then A stage 1 ----
#pragma unroll
    for (int c = 0; c < 8; c++) {
        size_t ob = (size_t)(col0 + br) * DHID + c * 32 + bs;
        cpa16(sb + (uint32_t)(OFF_B + c * ST_B + br * LDA + bs) * 2, Bh + ob, 16);
    }
    load_A(0, 0);
    asm volatile("cp.async.commit_group;");
    load_A(1, 1);
    asm volatile("cp.async.commit_group;");

    for (int kt = 0; kt < 8; kt++) {
        const int s = kt & 1;
        if (kt < 7) asm volatile("cp.async.wait_group 1;");
        else        asm volatile("cp.async.wait_group 0;");
        __syncthreads();

        const uint32_t aBase = sb + (uint32_t)(s * ST_A + aTerm + aTileOff) * 2;
        const uint32_t bBase = sb + (uint32_t)(OFF_B + kt * ST_B + bTerm + bTileOff) * 2;

#pragma unroll
        for (int kk = 0; kk < 32; kk += 16) {
            uint32_t ah[4][4], bh[4][2];
#pragma unroll
            for (int mt = 0; mt < 4; mt++) {
                uint32_t off = (uint32_t)(mt * 16 * LDA + kk) * 2;
                ldsm4(ah[mt], aBase + off);
            }
#pragma unroll
            for (int p = 0; p < 2; p++) {
                uint32_t off = (uint32_t)(p * 16 * LDA + kk) * 2;
                uint32_t t[4];
                ldsm4(t, bBase + off);
                bh[2 * p][0] = t[0]; bh[2 * p][1] = t[1];
                bh[2 * p + 1][0] = t[2]; bh[2 * p + 1][1] = t[3];
            }
#pragma unroll
            for (int mt = 0; mt < 4; mt++)
#pragma unroll
                for (int nt = 0; nt < 4; nt++)
                    mma_f16(acc[mt][nt], ah[mt], bh[nt]);
        }
        __syncthreads();

        if (kt < 6) {
            load_A(kt + 2, s);
            asm volatile("cp.async.commit_group;");
        }
    }

#pragma unroll
    for (int mt = 0; mt < 4; mt++) {
        int r0 = row0 + wm * 64 + mt * 16 + g;
#pragma unroll
        for (int half = 0; half < 2; half++) {
            int row = r0 + half * 8;
            if (row >= N_NODES) continue;
#pragma unroll
            for (int nt = 0; nt < 4; nt++) {
                int col = col0 + wn * 32 + nt * 8 + tg * 2;
                float c0 = acc[mt][nt][half * 2 + 0];
                float c1 = acc[mt][nt][half * 2 + 1];
                if (MODE == 0) {
                    c0 = fmaxf(c0 + __ldg(bias + col), 0.f);
                    c1 = fmaxf(c1 + __ldg(bias + col + 1), 0.f);
                    *reinterpret_cast<uint32_t*>(Ch + (size_t)row * DHID + col) = pack_f16(c0, c1);
                } else {
                    if (col0 == 0) {
                        *reinterpret_cast<uint32_t*>(Ch + (size_t)row * DIN + col) = pack_f16(c0, c1);
                    } else {
                        *reinterpret_cast<float2*>(Cq + (size_t)row * DIN + (col - 128)) =
                            make_float2(c0, c1);
                    }
                }
            }
        }
    }
}

// ---------------------------------------------------------------------------
extern "C" void kernel_launch(void* const* d_in, const int* in_sizes, int n_in,
                              void* d_out, int out_size) {
    const float* x   = (const float*)d_in[0];
    const int*   ei  = (const int*)d_in[1];
    const float* W1l = (const float*)d_in[2];
    const float* b1  = (const float*)d_in[3];
    const float* W1r = (const float*)d_in[4];
    const float* W2l = (const float*)d_in[5];
    const float* b2  = (const float*)d_in[6];
    const float* W2r = (const float*)d_in[7];
    float* out = (float*)d_out;

    const int E = in_sizes[1] / 2;
    const int* src = ei;
    const int* dst = ei + E;

    int *degi, *off, *cur, *esrc, *psum;
    float *q;
    uint16_t *x16, *am, *h16, *p16, *wh;
    cudaGetSymbolAddress((void**)&degi, g_degi);
    cudaGetSymbolAddress((void**)&off,  g_off);
    cudaGetSymbolAddress((void**)&cur,  g_cur);
    cudaGetSymbolAddress((void**)&esrc, g_esrc);
    cudaGetSymbolAddress((void**)&psum, g_psum);
    cudaGetSymbolAddress((void**)&x16,  g_x16);
    cudaGetSymbolAddress((void**)&am,   g_mean);
    cudaGetSymbolAddress((void**)&h16,  g_h16);
    cudaGetSymbolAddress((void**)&p16,  g_p16);
    cudaGetSymbolAddress((void**)&q,    g_q);
    cudaGetSymbolAddress((void**)&wh,   g_wh);

    const int SMEM = SMEM_ELEMS * 2;   // 122880 B
    static cudaStream_t s1 = nullptr;
    static cudaEvent_t evF, evJ;
    if (!s1) {
        cudaFuncSetAttribute(gemm_mma<0>, cudaFuncAttributeMaxDynamicSharedMemorySize, SMEM);
        cudaFuncSetAttribute(gemm_mma<1>, cudaFuncAttributeMaxDynamicSharedMemorySize, SMEM);
        cudaStreamCreateWithFlags(&s1, cudaStreamNonBlocking);
        cudaEventCreateWithFlags(&evF, cudaEventDisableTiming);
        cudaEventCreateWithFlags(&evJ, cudaEventDisableTiming);
    }

    const dim3 GG((N_NODES + 255) / 256, 2);
    const int AGG_GRID = (N_NODES + 7) / 8;

    // ---- fork: side stream runs the fused converts ----
    cudaEventRecord(evF, 0);
    cudaStreamWaitEvent(s1, evF, 0);
    conv_kernel<<<(N_NODES * DIN / 4 + 255) / 256, 256, 0, s1>>>(
        x, x16, W1l, W1r, W2l, W2r, wh);

    // ---- main stream: CSR build (parallel 3-phase scan) ----
    zero_int_kernel<<<(N_NODES + 255) / 256, 256>>>(degi, N_NODES);
    degi_kernel<<<(E + 255) / 256, 256>>>(dst, E, degi);
    scan1_kernel<<<SCAN_NB, 256>>>(degi, psum);
    scan2_kernel<<<1, 256>>>(psum);
    scan3_kernel<<<SCAN_NB, 256>>>(degi, psum, off, cur, E);
    fill_kernel<<<(E + 255) / 256, 256>>>(src, dst, off, cur, esrc, E);

    // ---- join converts before layer 1 ----
    cudaEventRecord(evJ, s1);
    cudaStreamWaitEvent(0, evJ, 0);

    // layer 1
    agg_csr_kernel<0><<<AGG_GRID, 256>>>(x16, off, esrc, am, nullptr, nullptr, nullptr);
    gemm_mma<0><<<GG, 512, SMEM>>>(am, x16, wh, b1, h16, nullptr);

    // layer 2
    gemm_mma<1><<<GG, 512, SMEM>>>(h16, nullptr, wh + DHID * DHID, nullptr, p16, q);
    agg_csr_kernel<1><<<AGG_GRID, 256>>>(p16, off, esrc, nullptr, q, b2, out);
}

// round 16
// speedup vs baseline: 1.0639x; 1.0639x over previous
#include <cuda_runtime.h>
#include <cuda_fp16.h>
#include <cstdint>
#include <cstddef>

#define N_NODES 50000
#define DIN 128
#define DHID 256
#define E_MAX 1000000
#define SCAN_NB ((N_NODES + 255) / 256)   // 196

// ---- scratch (static device globals; no allocation allowed) ----
__device__ int g_degi[N_NODES];
__device__ int g_off[N_NODES + 1];
__device__ int g_cur[N_NODES];
__device__ int g_esrc[E_MAX];
__device__ int g_psum[256];
__device__ uint16_t g_x16[N_NODES * DIN];      // x in fp16
__device__ uint16_t g_a1[N_NODES * DHID];      // layer1 A = [mean | x] fp16
__device__ uint16_t g_h16[N_NODES * DHID];     // relu(h) fp16
__device__ uint16_t g_p16[N_NODES * DIN];      // p = h@W2l^T fp16
__device__ float    g_q[N_NODES * DIN];        // q = h@W2r^T fp32
__device__ uint16_t g_wh[2 * DHID * DHID];     // weights fp16

// ---------------------------------------------------------------------------
__device__ __forceinline__ uint32_t smem_u32(const void* p) {
    uint32_t a;
    asm("{ .reg .u64 t; cvta.to.shared.u64 t, %1; cvt.u32.u64 %0, t; }" : "=r"(a) : "l"(p));
    return a;
}
__device__ __forceinline__ uint32_t pack_f16(float x, float y) {
    __half2 t = __floats2half2_rn(x, y);
    return *reinterpret_cast<uint32_t*>(&t);
}
__device__ __forceinline__ void cpa16(uint32_t saddr, const void* g, int sz) {
    asm volatile("cp.async.cg.shared.global [%0], [%1], 16, %2;" :: "r"(saddr), "l"(g), "r"(sz));
}
__device__ __forceinline__ void mma_f16(float* c, const uint32_t* a, const uint32_t* b) {
    asm volatile(
        "mma.sync.aligned.m16n8k16.row.col.f32.f16.f16.f32 "
        "{%0,%1,%2,%3}, {%4,%5,%6,%7}, {%8,%9}, {%0,%1,%2,%3};"
        : "+f"(c[0]), "+f"(c[1]), "+f"(c[2]), "+f"(c[3])
        : "r"(a[0]), "r"(a[1]), "r"(a[2]), "r"(a[3]), "r"(b[0]), "r"(b[1]));
}
__device__ __forceinline__ void ldsm4(uint32_t* r, uint32_t a) {
    asm volatile("ldmatrix.sync.aligned.m8n8.x4.shared.b16 {%0,%1,%2,%3}, [%4];"
                 : "=r"(r[0]), "=r"(r[1]), "=r"(r[2]), "=r"(r[3]) : "r"(a));
}
__device__ __forceinline__ void acc_u2(float4& a, uint2 u) {
    float2 lo = __half22float2(*reinterpret_cast<__half2*>(&u.x));
    float2 hi = __half22float2(*reinterpret_cast<__half2*>(&u.y));
    a.x += lo.x; a.y += lo.y; a.z += hi.x; a.w += hi.y;
}

// ---------------------------------------------------------------------------
// CSR build
// ---------------------------------------------------------------------------
__global__ void zero_int_kernel(int* __restrict__ p, int n) {
    int i = blockIdx.x * blockDim.x + threadIdx.x;
    if (i < n) p[i] = 0;
}
__global__ void degi_kernel(const int* __restrict__ dst, int E, int* __restrict__ degi) {
    int i = blockIdx.x * blockDim.x + threadIdx.x;
    if (i < E) atomicAdd(&degi[dst[i]], 1);
}

// --- 3-phase device-wide exclusive scan of degi -> off ---
__global__ void scan1_kernel(const int* __restrict__ degi, int* __restrict__ psum) {
    __shared__ int sh[256];
    int i = blockIdx.x * 256 + threadIdx.x;
    sh[threadIdx.x] = (i < N_NODES) ? degi[i] : 0;
    __syncthreads();
#pragma unroll
    for (int o = 128; o > 0; o >>= 1) {
        if (threadIdx.x < o) sh[threadIdx.x] += sh[threadIdx.x + o];
        __syncthreads();
    }
    if (threadIdx.x == 0) psum[blockIdx.x] = sh[0];
}
__global__ void scan2_kernel(int* __restrict__ psum) {
    __shared__ int sh[256];
    int t = threadIdx.x;
    sh[t] = (t < SCAN_NB) ? psum[t] : 0;
    __syncthreads();
#pragma unroll
    for (int o = 1; o < 256; o <<= 1) {
        int u = (t >= o) ? sh[t - o] : 0;
        __syncthreads();
        sh[t] += u;
        __syncthreads();
    }
    if (t < SCAN_NB) psum[t] = (t == 0) ? 0 : sh[t - 1];
}
__global__ void scan3_kernel(const int* __restrict__ degi, const int* __restrict__ psum,
                             int* __restrict__ off, int* __restrict__ cur, int E) {
    const int t = threadIdx.x, b = blockIdx.x;
    const int i = b * 256 + t;
    const int lane = t & 31, w = t >> 5;
    int v = (i < N_NODES) ? degi[i] : 0;
    int s = v;
#pragma unroll
    for (int o = 1; o < 32; o <<= 1) {
        int u = __shfl_up_sync(0xffffffffu, s, o);
        if (lane >= o) s += u;
    }
    __shared__ int wsum[8];
    if (lane == 31) wsum[w] = s;
    __syncthreads();
    if (t < 8) {
        int ws = wsum[t];
#pragma unroll
        for (int o = 1; o < 8; o <<= 1) {
            int u = __shfl_up_sync(0xffu, ws, o);
            if (t >= o) ws += u;
        }
        wsum[t] = ws;
    }
    __syncthreads();
    int base = __ldg(psum + b) + ((w > 0) ? wsum[w - 1] : 0);
    if (i < N_NODES) {
        off[i] = base + s - v;   // exclusive
        cur[i] = 0;
    }
    if (i == 0) off[N_NODES] = E;
}

// two edges per thread, vectorized index loads
__global__ void fill_kernel(const int* __restrict__ src, const int* __restrict__ dst,
                            const int* __restrict__ off, int* __restrict__ cur,
                            int* __restrict__ esrc, int E) {
    int t = blockIdx.x * blockDim.x + threadIdx.x;
    int e0 = t * 2;
    if (e0 >= E) return;
    if (e0 + 1 < E) {
        int2 d2 = *reinterpret_cast<const int2*>(dst + e0);
        int2 s2 = *reinterpret_cast<const int2*>(src + e0);
        int p0 = atomicAdd(&cur[d2.x], 1);
        esrc[__ldg(off + d2.x) + p0] = s2.x;
        int p1 = atomicAdd(&cur[d2.y], 1);
        esrc[__ldg(off + d2.y) + p1] = s2.y;
    } else {
        int d = dst[e0];
        int p = atomicAdd(&cur[d], 1);
        esrc[off[d] + p] = src[e0];
    }
}

// ---------------------------------------------------------------------------
// fused convert: x -> fp16 (all threads) ; weights -> fp16 (first 32768 threads)
// ---------------------------------------------------------------------------
__global__ void conv_kernel(const float* __restrict__ x, uint16_t* __restrict__ x16,
                            const float* __restrict__ W1l, const float* __restrict__ W1r,
                            const float* __restrict__ W2l, const float* __restrict__ W2r,
                            uint16_t* __restrict__ wh) {
    int t = blockIdx.x * blockDim.x + threadIdx.x;
    if (t < N_NODES * DIN / 4) {
        float4 v = *reinterpret_cast<const float4*>(x + (size_t)t * 4);
        uint2 o;
        o.x = pack_f16(v.x, v.y);
        o.y = pack_f16(v.z, v.w);
        reinterpret_cast<uint2*>(x16)[t] = o;
    }
    if (t < 2 * DHID * DHID / 4) {
        int layer = t >> 14;
        int e0 = (t & 16383) * 4;
        int j = e0 >> 8, k = e0 & 255;
        float4 v;
        if (layer == 0) {
            v = (k < DIN) ? *reinterpret_cast<const float4*>(W1l + (size_t)j * DIN + k)
                          : *reinterpret_cast<const float4*>(W1r + (size_t)j * DIN + (k - DIN));
        } else {
            v = (j < 128) ? *reinterpret_cast<const float4*>(W2l + (size_t)j * DHID + k)
                          : *reinterpret_cast<const float4*>(W2r + (size_t)(j - 128) * DHID + k);
        }
        size_t o = (size_t)layer * DHID * DHID + e0;
        *reinterpret_cast<uint32_t*>(wh + o)     = pack_f16(v.x, v.y);
        *reinterpret_cast<uint32_t*>(wh + o + 2) = pack_f16(v.z, v.w);
    }
}

// ---------------------------------------------------------------------------
// CSR aggregation over fp16 features, one warp per node, 8-edge unroll.
// MODE 0: feat16 = x16. epilogue: A1 = [mean | x16] fp16
// MODE 1: feat16 = p16. epilogue: out = mean + q + b2 (fp32)
// ---------------------------------------------------------------------------
template <int MODE>
__global__ __launch_bounds__(256)
void agg_csr_kernel(const uint16_t* __restrict__ feat16,
                    const int* __restrict__ off, const int* __restrict__ esrc,
                    uint16_t* __restrict__ a1,
                    const float* __restrict__ q, const float* __restrict__ b2,
                    float* __restrict__ out) {
    const int d = blockIdx.x * 8 + (threadIdx.x >> 5);
    if (d >= N_NODES) return;
    const int lane = threadIdx.x & 31;
    const uint2* F = reinterpret_cast<const uint2*>(feat16);

    const int beg = __ldg(off + d);
    const int end = __ldg(off + d + 1);

    float4 acc0 = make_float4(0.f, 0.f, 0.f, 0.f);
    float4 acc1 = acc0, acc2 = acc0, acc3 = acc0;
    int i = beg;
    for (; i + 8 <= end; i += 8) {
        int s0 = __ldg(esrc + i),     s1 = __ldg(esrc + i + 1);
        int s2 = __ldg(esrc + i + 2), s3 = __ldg(esrc + i + 3);
        int s4 = __ldg(esrc + i + 4), s5 = __ldg(esrc + i + 5);
        int s6 = __ldg(esrc + i + 6), s7 = __ldg(esrc + i + 7);
        uint2 u0 = __ldg(F + (size_t)s0 * 32 + lane);
        uint2 u1 = __ldg(F + (size_t)s1 * 32 + lane);
        uint2 u2 = __ldg(F + (size_t)s2 * 32 + lane);
        uint2 u3 = __ldg(F + (size_t)s3 * 32 + lane);
        uint2 u4 = __ldg(F + (size_t)s4 * 32 + lane);
        uint2 u5 = __ldg(F + (size_t)s5 * 32 + lane);
        uint2 u6 = __ldg(F + (size_t)s6 * 32 + lane);
        uint2 u7 = __ldg(F + (size_t)s7 * 32 + lane);
        acc_u2(acc0, u0); acc_u2(acc1, u1); acc_u2(acc2, u2); acc_u2(acc3, u3);
        acc_u2(acc0, u4); acc_u2(acc1, u5); acc_u2(acc2, u6); acc_u2(acc3, u7);
    }
    for (; i + 4 <= end; i += 4) {
        int s0 = __ldg(esrc + i),     s1 = __ldg(esrc + i + 1);
        int s2 = __ldg(esrc + i + 2), s3 = __ldg(esrc + i + 3);
        uint2 u0 = __ldg(F + (size_t)s0 * 32 + lane);
        uint2 u1 = __ldg(F + (size_t)s1 * 32 + lane);
        uint2 u2 = __ldg(F + (size_t)s2 * 32 + lane);
        uint2 u3 = __ldg(F + (size_t)s3 * 32 + lane);
        acc_u2(acc0, u0); acc_u2(acc1, u1); acc_u2(acc2, u2); acc_u2(acc3, u3);
    }
    for (; i < end; i++) {
        int s = __ldg(esrc + i);
        uint2 u = __ldg(F + (size_t)s * 32 + lane);
        acc_u2(acc0, u);
    }
    float4 acc;
    acc.x = (acc0.x + acc1.x) + (acc2.x + acc3.x);
    acc.y = (acc0.y + acc1.y) + (acc2.y + acc3.y);
    acc.z = (acc0.z + acc1.z) + (acc2.z + acc3.z);
    acc.w = (acc0.w + acc1.w) + (acc2.w + acc3.w);

    const float rd = 1.0f / (float)max(end - beg, 1);
    acc.x *= rd; acc.y *= rd; acc.z *= rd; acc.w *= rd;

    if (MODE == 0) {
        uint2 o;
        o.x = pack_f16(acc.x, acc.y);
        o.y = pack_f16(acc.z, acc.w);
        reinterpret_cast<uint2*>(a1 + (size_t)d * DHID)[lane] = o;
        uint2 xv = __ldg(F + (size_t)d * 32 + lane);
        reinterpret_cast<uint2*>(a1 + (size_t)d * DHID + DIN)[lane] = xv;
    } else {
        float4 qv = __ldg(reinterpret_cast<const float4*>(q) + (size_t)d * 32 + lane);
        float4 bb = __ldg(reinterpret_cast<const float4*>(b2) + lane);
        float4 o;
        o.x = acc.x + qv.x + bb.x;
        o.y = acc.y + qv.y + bb.y;
        o.z = acc.z + qv.z + bb.z;
        o.w = acc.w + qv.w + bb.w;
        reinterpret_cast<float4*>(out)[(size_t)d * 32 + lane] = o;
    }
}

// ---------------------------------------------------------------------------
// fp16 GEMM: C = A @ B^T, 256x128 tile, 512 threads, cp.async double buffer.
// (exact R14-proven configuration)
// MODE 0: epilogue relu(+bias) -> fp16 Ch (ld 256)
// MODE 1: epilogue split: col0==0 -> fp16 p16 (ld 128); col0==128 -> fp32 q (ld 128)
// ---------------------------------------------------------------------------
#define LDA 40
#define ST_A (256 * LDA)
#define ST_B (128 * LDA)
#define ST_TOTAL (ST_A + ST_B)
#define OFF_BH ST_A

template <int MODE>
__global__ __launch_bounds__(512, 1)
void gemm_mma(const uint16_t* __restrict__ Ah, const uint16_t* __restrict__ Bh,
              const float* __restrict__ bias,
              uint16_t* __restrict__ Ch, float* __restrict__ Cq) {
    extern __shared__ __align__(16) uint16_t smem[];
    const uint32_t sb = smem_u32(smem);

    const int tid  = threadIdx.x;
    const int wid  = tid >> 5;
    const int lane = tid & 31;
    const int g    = lane >> 2;
    const int tg   = lane & 3;
    const int row0 = blockIdx.x * 256;
    const int col0 = blockIdx.y * 128;
    const int wm   = wid >> 2;
    const int wn   = wid & 3;

    const int qa0 = tid * 2;
    const int ar0 = qa0 >> 2, as0 = (qa0 & 3) * 8;
    const int ar1 = (qa0 + 1) >> 2, as1 = ((qa0 + 1) & 3) * 8;
    const int br = tid >> 2, bs = (tid & 3) * 8;

    const int aTerm = (lane & 15) * LDA + (lane >> 4) * 8;
    const int bTerm = ((lane & 7) + ((lane >> 4) << 3)) * LDA + ((lane >> 3) & 1) * 8;
    const int aTileOff = (wm * 64) * LDA;
    const int bTileOff = (wn * 32) * LDA;

    float acc[4][4][4];
#pragma unroll
    for (int i = 0; i < 4; i++)
#pragma unroll
        for (int j = 0; j < 4; j++)
#pragma unroll
            for (int k = 0; k < 4; k++) acc[i][j][k] = 0.f;

    auto load_stage = [&](int kt, int s) {
        const int k0 = kt * 32;
        const uint32_t sbase = sb + (uint32_t)(s * ST_TOTAL) * 2;
        {
            int r0a = row0 + ar0, r1a = row0 + ar1;
            int sz0 = (r0a < N_NODES) ? 16 : 0;
            int sz1 = (r1a < N_NODES) ? 16 : 0;
            size_t o0 = (size_t)min(r0a, N_NODES - 1) * DHID + k0 + as0;
            size_t o1 = (size_t)min(r1a, N_NODES - 1) * DHID + k0 + as1;
            cpa16(sbase + (ar0 * LDA + as0) * 2, Ah + o0, sz0);
            cpa16(sbase + (ar1 * LDA + as1) * 2, Ah + o1, sz1);
        }
        {
            size_t ob = (size_t)(col0 + br) * DHID + k0 + bs;
            cpa16(sbase + (OFF_BH + br * LDA + bs) * 2, Bh + ob, 16);
        }
        asm volatile("cp.async.commit_group;");
    };

    load_stage(0, 0);

    for (int kt = 0; kt < 8; kt++) {
        const int s = kt & 1;
        if (kt < 7) load_stage(kt + 1, s ^ 1);
        if (kt < 7) asm volatile("cp.async.wait_group 1;");
        else        asm volatile("cp.async.wait_group 0;");
        __syncthreads();

        const uint32_t stg = sb + (uint32_t)(s * ST_TOTAL) * 2;
        const uint32_t aBase = stg + (uint32_t)(aTerm + aTileOff) * 2;
        const uint32_t bBase = stg + (uint32_t)(OFF_BH + bTerm + bTileOff) * 2;

#pragma unroll
        for (int kk = 0; kk < 32; kk += 16) {
            uint32_t ah[4][4], bh[4][2];
#pragma unroll
            for (int mt = 0; mt < 4; mt++) {
                uint32_t off = (uint32_t)(mt * 16 * LDA + kk) * 2;
                ldsm4(ah[mt], aBase + off);
            }
#pragma unroll
            for (int p = 0; p < 2; p++) {
                uint32_t off = (uint32_t)(p * 16 * LDA + kk) * 2;
                uint32_t t[4];
                ldsm4(t, bBase + off);
                bh[2 * p][0] = t[0]; bh[2 * p][1] = t[1];
                bh[2 * p + 1][0] = t[2]; bh[2 * p + 1][1] = t[3];
            }
#pragma unroll
            for (int mt = 0; mt < 4; mt++)
#pragma unroll
                for (int nt = 0; nt < 4; nt++)
                    mma_f16(acc[mt][nt], ah[mt], bh[nt]);
        }
        __syncthreads();
    }

#pragma unroll
    for (int mt = 0; mt < 4; mt++) {
        int r0 = row0 + wm * 64 + mt * 16 + g;
#pragma unroll
        for (int half = 0; half < 2; half++) {
            int row = r0 + half * 8;
            if (row >= N_NODES) continue;
#pragma unroll
            for (int nt = 0; nt < 4; nt++) {
                int col = col0 + wn * 32 + nt * 8 + tg * 2;
                float c0 = acc[mt][nt][half * 2 + 0];
                float c1 = acc[mt][nt][half * 2 + 1];
                if (MODE == 0) {
                    c0 = fmaxf(c0 + __ldg(bias + col), 0.f);
                    c1 = fmaxf(c1 + __ldg(bias + col + 1), 0.f);
                    *reinterpret_cast<uint32_t*>(Ch + (size_t)row * DHID + col) = pack_f16(c0, c1);
                } else {
                    if (col0 == 0) {
                        *reinterpret_cast<uint32_t*>(Ch + (size_t)row * DIN + col) = pack_f16(c0, c1);
                    } else {
                        *reinterpret_cast<float2*>(Cq + (size_t)row * DIN + (col - 128)) =
                            make_float2(c0, c1);
                    }
                }
            }
        }
    }
}

// ---------------------------------------------------------------------------
extern "C" void kernel_launch(void* const* d_in, const int* in_sizes, int n_in,
                              void* d_out, int out_size) {
    const float* x   = (const float*)d_in[0];
    const int*   ei  = (const int*)d_in[1];
    const float* W1l = (const float*)d_in[2];
    const float* b1  = (const float*)d_in[3];
    const float* W1r = (const float*)d_in[4];
    const float* W2l = (const float*)d_in[5];
    const float* b2  = (const float*)d_in[6];
    const float* W2r = (const float*)d_in[7];
    float* out = (float*)d_out;

    const int E = in_sizes[1] / 2;
    const int* src = ei;
    const int* dst = ei + E;

    int *degi, *off, *cur, *esrc, *psum;
    float *q;
    uint16_t *x16, *a1, *h16, *p16, *wh;
    cudaGetSymbolAddress((void**)&degi, g_degi);
    cudaGetSymbolAddress((void**)&off,  g_off);
    cudaGetSymbolAddress((void**)&cur,  g_cur);
    cudaGetSymbolAddress((void**)&esrc, g_esrc);
    cudaGetSymbolAddress((void**)&psum, g_psum);
    cudaGetSymbolAddress((void**)&x16,  g_x16);
    cudaGetSymbolAddress((void**)&a1,   g_a1);
    cudaGetSymbolAddress((void**)&h16,  g_h16);
    cudaGetSymbolAddress((void**)&p16,  g_p16);
    cudaGetSymbolAddress((void**)&q,    g_q);
    cudaGetSymbolAddress((void**)&wh,   g_wh);

    const int SMEM = 2 * ST_TOTAL * 2;   // 61440 B
    static cudaStream_t s1 = nullptr;
    static cudaEvent_t evF, evJ;
    if (!s1) {
        cudaFuncSetAttribute(gemm_mma<0>, cudaFuncAttributeMaxDynamicSharedMemorySize, SMEM);
        cudaFuncSetAttribute(gemm_mma<1>, cudaFuncAttributeMaxDynamicSharedMemorySize, SMEM);
        cudaStreamCreateWithFlags(&s1, cudaStreamNonBlocking);
        cudaEventCreateWithFlags(&evF, cudaEventDisableTiming);
        cudaEventCreateWithFlags(&evJ, cudaEventDisableTiming);
    }

    const dim3 GG((N_NODES + 255) / 256, 2);
    const int AGG_GRID = (N_NODES + 7) / 8;

    // ---- fork: side stream runs the fused converts ----
    cudaEventRecord(evF, 0);
    cudaStreamWaitEvent(s1, evF, 0);
    conv_kernel<<<(N_NODES * DIN / 4 + 255) / 256, 256, 0, s1>>>(
        x, x16, W1l, W1r, W2l, W2r, wh);

    // ---- main stream: CSR build (parallel 3-phase scan) ----
    zero_int_kernel<<<(N_NODES + 255) / 256, 256>>>(degi, N_NODES);
    degi_kernel<<<(E + 255) / 256, 256>>>(dst, E, degi);
    scan1_kernel<<<SCAN_NB, 256>>>(degi, psum);
    scan2_kernel<<<1, 256>>>(psum);
    scan3_kernel<<<SCAN_NB, 256>>>(degi, psum, off, cur, E);
    fill_kernel<<<((E + 1) / 2 + 255) / 256, 256>>>(src, dst, off, cur, esrc, E);

    // ---- join converts before layer 1 ----
    cudaEventRecord(evJ, s1);
    cudaStreamWaitEvent(0, evJ, 0);

    // layer 1
    agg_csr_kernel<0><<<AGG_GRID, 256>>>(x16, off, esrc, a1, nullptr, nullptr, nullptr);
    gemm_mma<0><<<GG, 512, SMEM>>>(a1, wh, b1, h16, nullptr);

    // layer 2
    gemm_mma<1><<<GG, 512, SMEM>>>(h16, wh + DHID * DHID, nullptr, p16, q);
    agg_csr_kernel<1><<<AGG_GRID, 256>>>(p16, off, esrc, nullptr, q, b2, out);
}

// round 17
// speedup vs baseline: 1.0798x; 1.0150x over previous
#include <cuda_runtime.h>
#include <cuda_fp16.h>
#include <cstdint>
#include <cstddef>

#define N_NODES 50000
#define DIN 128
#define DHID 256
#define E_MAX 1000000
#define SCAN_NB ((N_NODES + 255) / 256)   // 196

// ---- scratch (static device globals; no allocation allowed) ----
__device__ int g_degi[N_NODES];
__device__ int g_off[N_NODES + 1];
__device__ int g_cur[N_NODES];
__device__ int g_esrc[E_MAX];
__device__ int g_psum[256];
__device__ uint16_t g_x16[N_NODES * DIN];      // x in fp16
__device__ uint16_t g_a1[N_NODES * DHID];      // layer1 A = [mean | x] fp16
__device__ uint16_t g_h16[N_NODES * DHID];     // relu(h) fp16
__device__ uint16_t g_p16[N_NODES * DIN];      // p = h@W2l^T fp16
__device__ float    g_q[N_NODES * DIN];        // q = h@W2r^T fp32
__device__ uint16_t g_wh[2 * DHID * DHID];     // weights fp16

// ---------------------------------------------------------------------------
__device__ __forceinline__ uint32_t smem_u32(const void* p) {
    uint32_t a;
    asm("{ .reg .u64 t; cvta.to.shared.u64 t, %1; cvt.u32.u64 %0, t; }" : "=r"(a) : "l"(p));
    return a;
}
__device__ __forceinline__ uint32_t pack_f16(float x, float y) {
    __half2 t = __floats2half2_rn(x, y);
    return *reinterpret_cast<uint32_t*>(&t);
}
__device__ __forceinline__ void cpa16(uint32_t saddr, const void* g, int sz) {
    asm volatile("cp.async.cg.shared.global [%0], [%1], 16, %2;" :: "r"(saddr), "l"(g), "r"(sz));
}
__device__ __forceinline__ void mma_f16(float* c, const uint32_t* a, const uint32_t* b) {
    asm volatile(
        "mma.sync.aligned.m16n8k16.row.col.f32.f16.f16.f32 "
        "{%0,%1,%2,%3}, {%4,%5,%6,%7}, {%8,%9}, {%0,%1,%2,%3};"
        : "+f"(c[0]), "+f"(c[1]), "+f"(c[2]), "+f"(c[3])
        : "r"(a[0]), "r"(a[1]), "r"(a[2]), "r"(a[3]), "r"(b[0]), "r"(b[1]));
}
__device__ __forceinline__ void ldsm4(uint32_t* r, uint32_t a) {
    asm volatile("ldmatrix.sync.aligned.m8n8.x4.shared.b16 {%0,%1,%2,%3}, [%4];"
                 : "=r"(r[0]), "=r"(r[1]), "=r"(r[2]), "=r"(r[3]) : "r"(a));
}
__device__ __forceinline__ void acc_u2(float4& a, uint2 u) {
    float2 lo = __half22float2(*reinterpret_cast<__half2*>(&u.x));
    float2 hi = __half22float2(*reinterpret_cast<__half2*>(&u.y));
    a.x += lo.x; a.y += lo.y; a.z += hi.x; a.w += hi.y;
}

// ---------------------------------------------------------------------------
// CSR build
// ---------------------------------------------------------------------------
__global__ void zero_int_kernel(int* __restrict__ p, int n) {
    int i = blockIdx.x * blockDim.x + threadIdx.x;
    if (i < n) p[i] = 0;
}
__global__ void degi_kernel(const int* __restrict__ dst, int E, int* __restrict__ degi) {
    int i = blockIdx.x * blockDim.x + threadIdx.x;
    if (i < E) atomicAdd(&degi[dst[i]], 1);
}

// per-256-chunk sums of degi -> psum (raw, unscanned)
__global__ void scan1_kernel(const int* __restrict__ degi, int* __restrict__ psum) {
    __shared__ int sh[256];
    int i = blockIdx.x * 256 + threadIdx.x;
    sh[threadIdx.x] = (i < N_NODES) ? degi[i] : 0;
    __syncthreads();
#pragma unroll
    for (int o = 128; o > 0; o >>= 1) {
        if (threadIdx.x < o) sh[threadIdx.x] += sh[threadIdx.x + o];
        __syncthreads();
    }
    if (threadIdx.x == 0) psum[blockIdx.x] = sh[0];
}

// fused: block b reduces psum[0..b-1] itself (no separate scan2 launch),
// then block-local exclusive scan of degi -> off; zero cur.
__global__ void scan3_kernel(const int* __restrict__ degi, const int* __restrict__ psum,
                             int* __restrict__ off, int* __restrict__ cur, int E) {
    const int t = threadIdx.x, b = blockIdx.x;
    __shared__ int red[256];
    red[t] = (t < b) ? __ldg(psum + t) : 0;
    __syncthreads();
#pragma unroll
    for (int o = 128; o > 0; o >>= 1) {
        if (t < o) red[t] += red[t + o];
        __syncthreads();
    }
    const int blockBase = red[0];

    const int i = b * 256 + t;
    const int lane = t & 31, w = t >> 5;
    int v = (i < N_NODES) ? degi[i] : 0;
    int s = v;
#pragma unroll
    for (int o = 1; o < 32; o <<= 1) {
        int u = __shfl_up_sync(0xffffffffu, s, o);
        if (lane >= o) s += u;
    }
    __shared__ int wsum[8];
    if (lane == 31) wsum[w] = s;
    __syncthreads();
    if (t < 8) {
        int ws = wsum[t];
#pragma unroll
        for (int o = 1; o < 8; o <<= 1) {
            int u = __shfl_up_sync(0xffu, ws, o);
            if (t >= o) ws += u;
        }
        wsum[t] = ws;
    }
    __syncthreads();
    int base = blockBase + ((w > 0) ? wsum[w - 1] : 0);
    if (i < N_NODES) {
        off[i] = base + s - v;   // exclusive
        cur[i] = 0;
    }
    if (i == 0) off[N_NODES] = E;
}

// two edges per thread, vectorized index loads
__global__ void fill_kernel(const int* __restrict__ src, const int* __restrict__ dst,
                            const int* __restrict__ off, int* __restrict__ cur,
                            int* __restrict__ esrc, int E) {
    int t = blockIdx.x * blockDim.x + threadIdx.x;
    int e0 = t * 2;
    if (e0 >= E) return;
    if (e0 + 1 < E) {
        int2 d2 = *reinterpret_cast<const int2*>(dst + e0);
        int2 s2 = *reinterpret_cast<const int2*>(src + e0);
        int p0 = atomicAdd(&cur[d2.x], 1);
        esrc[__ldg(off + d2.x) + p0] = s2.x;
        int p1 = atomicAdd(&cur[d2.y], 1);
        esrc[__ldg(off + d2.y) + p1] = s2.y;
    } else {
        int d = dst[e0];
        int p = atomicAdd(&cur[d], 1);
        esrc[off[d] + p] = src[e0];
    }
}

// ---------------------------------------------------------------------------
// fused convert: x -> fp16 (all threads) ; weights -> fp16 (first 32768 threads)
// ---------------------------------------------------------------------------
__global__ void conv_kernel(const float* __restrict__ x, uint16_t* __restrict__ x16,
                            const float* __restrict__ W1l, const float* __restrict__ W1r,
                            const float* __restrict__ W2l, const float* __restrict__ W2r,
                            uint16_t* __restrict__ wh) {
    int t = blockIdx.x * blockDim.x + threadIdx.x;
    if (t < N_NODES * DIN / 4) {
        float4 v = *reinterpret_cast<const float4*>(x + (size_t)t * 4);
        uint2 o;
        o.x = pack_f16(v.x, v.y);
        o.y = pack_f16(v.z, v.w);
        reinterpret_cast<uint2*>(x16)[t] = o;
    }
    if (t < 2 * DHID * DHID / 4) {
        int layer = t >> 14;
        int e0 = (t & 16383) * 4;
        int j = e0 >> 8, k = e0 & 255;
        float4 v;
        if (layer == 0) {
            v = (k < DIN) ? *reinterpret_cast<const float4*>(W1l + (size_t)j * DIN + k)
                          : *reinterpret_cast<const float4*>(W1r + (size_t)j * DIN + (k - DIN));
        } else {
            v = (j < 128) ? *reinterpret_cast<const float4*>(W2l + (size_t)j * DHID + k)
                          : *reinterpret_cast<const float4*>(W2r + (size_t)(j - 128) * DHID + k);
        }
        size_t o = (size_t)layer * DHID * DHID + e0;
        *reinterpret_cast<uint32_t*>(wh + o)     = pack_f16(v.x, v.y);
        *reinterpret_cast<uint32_t*>(wh + o + 2) = pack_f16(v.z, v.w);
    }
}

// ---------------------------------------------------------------------------
// CSR aggregation over fp16 features, one warp per node, 8-edge unroll.
// MODE 0: feat16 = x16. epilogue: A1 = [mean | x16] fp16
// MODE 1: feat16 = p16. epilogue: out = mean + q + b2 (fp32)
// ---------------------------------------------------------------------------
template <int MODE>
__global__ __launch_bounds__(256)
void agg_csr_kernel(const uint16_t* __restrict__ feat16,
                    const int* __restrict__ off, const int* __restrict__ esrc,
                    uint16_t* __restrict__ a1,
                    const float* __restrict__ q, const float* __restrict__ b2,
                    float* __restrict__ out) {
    const int d = blockIdx.x * 8 + (threadIdx.x >> 5);
    if (d >= N_NODES) return;
    const int lane = threadIdx.x & 31;
    const uint2* F = reinterpret_cast<const uint2*>(feat16);

    const int beg = __ldg(off + d);
    const int end = __ldg(off + d + 1);

    float4 acc0 = make_float4(0.f, 0.f, 0.f, 0.f);
    float4 acc1 = acc0, acc2 = acc0, acc3 = acc0;
    int i = beg;
    for (; i + 8 <= end; i += 8) {
        int s0 = __ldg(esrc + i),     s1 = __ldg(esrc + i + 1);
        int s2 = __ldg(esrc + i + 2), s3 = __ldg(esrc + i + 3);
        int s4 = __ldg(esrc + i + 4), s5 = __ldg(esrc + i + 5);
        int s6 = __ldg(esrc + i + 6), s7 = __ldg(esrc + i + 7);
        uint2 u0 = __ldg(F + (size_t)s0 * 32 + lane);
        uint2 u1 = __ldg(F + (size_t)s1 * 32 + lane);
        uint2 u2 = __ldg(F + (size_t)s2 * 32 + lane);
        uint2 u3 = __ldg(F + (size_t)s3 * 32 + lane);
        uint2 u4 = __ldg(F + (size_t)s4 * 32 + lane);
        uint2 u5 = __ldg(F + (size_t)s5 * 32 + lane);
        uint2 u6 = __ldg(F + (size_t)s6 * 32 + lane);
        uint2 u7 = __ldg(F + (size_t)s7 * 32 + lane);
        acc_u2(acc0, u0); acc_u2(acc1, u1); acc_u2(acc2, u2); acc_u2(acc3, u3);
        acc_u2(acc0, u4); acc_u2(acc1, u5); acc_u2(acc2, u6); acc_u2(acc3, u7);
    }
    for (; i + 4 <= end; i += 4) {
        int s0 = __ldg(esrc + i),     s1 = __ldg(esrc + i + 1);
        int s2 = __ldg(esrc + i + 2), s3 = __ldg(esrc + i + 3);
        uint2 u0 = __ldg(F + (size_t)s0 * 32 + lane);
        uint2 u1 = __ldg(F + (size_t)s1 * 32 + lane);
        uint2 u2 = __ldg(F + (size_t)s2 * 32 + lane);
        uint2 u3 = __ldg(F + (size_t)s3 * 32 + lane);
        acc_u2(acc0, u0); acc_u2(acc1, u1); acc_u2(acc2, u2); acc_u2(acc3, u3);
    }
    for (; i < end; i++) {
        int s = __ldg(esrc + i);
        uint2 u = __ldg(F + (size_t)s * 32 + lane);
        acc_u2(acc0, u);
    }
    float4 acc;
    acc.x = (acc0.x + acc1.x) + (acc2.x + acc3.x);
    acc.y = (acc0.y + acc1.y) + (acc2.y + acc3.y);
    acc.z = (acc0.z + acc1.z) + (acc2.z + acc3.z);
    acc.w = (acc0.w + acc1.w) + (acc2.w + acc3.w);

    const float rd = 1.0f / (float)max(end - beg, 1);
    acc.x *= rd; acc.y *= rd; acc.z *= rd; acc.w *= rd;

    if (MODE == 0) {
        uint2 o;
        o.x = pack_f16(acc.x, acc.y);
        o.y = pack_f16(acc.z, acc.w);
        reinterpret_cast<uint2*>(a1 + (size_t)d * DHID)[lane] = o;
        uint2 xv = __ldg(F + (size_t)d * 32 + lane);
        reinterpret_cast<uint2*>(a1 + (size_t)d * DHID + DIN)[lane] = xv;
    } else {
        float4 qv = __ldg(reinterpret_cast<const float4*>(q) + (size_t)d * 32 + lane);
        float4 bb = __ldg(reinterpret_cast<const float4*>(b2) + lane);
        float4 o;
        o.x = acc.x + qv.x + bb.x;
        o.y = acc.y + qv.y + bb.y;
        o.z = acc.z + qv.z + bb.z;
        o.w = acc.w + qv.w + bb.w;
        reinterpret_cast<float4*>(out)[(size_t)d * 32 + lane] = o;
    }
}

// ---------------------------------------------------------------------------
// fp16 GEMM: C = A @ B^T, 256x128 tile, 512 threads.
// 3-stage cp.async ring, ONE __syncthreads per stage (load for stage kt+2 is
// issued after the barrier proving all warps finished stage kt-1, which owns
// the same buffer: (kt+2) % 3 == (kt-1) % 3).
// MODE 0: epilogue relu(+bias) -> fp16 Ch (ld 256)
// MODE 1: epilogue split: col0==0 -> fp16 p16 (ld 128); col0==128 -> fp32 q (ld 128)
// ---------------------------------------------------------------------------
#define LDA 40
#define ST_A (256 * LDA)
#define ST_B (128 * LDA)
#define ST_TOTAL (ST_A + ST_B)
#define OFF_BH ST_A

template <int MODE>
__global__ __launch_bounds__(512, 1)
void gemm_mma(const uint16_t* __restrict__ Ah, const uint16_t* __restrict__ Bh,
              const float* __restrict__ bias,
              uint16_t* __restrict__ Ch, float* __restrict__ Cq) {
    extern __shared__ __align__(16) uint16_t smem[];
    const uint32_t sb = smem_u32(smem);

    const int tid  = threadIdx.x;
    const int wid  = tid >> 5;
    const int lane = tid & 31;
    const int g    = lane >> 2;
    const int tg   = lane & 3;
    const int row0 = blockIdx.x * 256;
    const int col0 = blockIdx.y * 128;
    const int wm   = wid >> 2;
    const int wn   = wid & 3;

    const int qa0 = tid * 2;
    const int ar0 = qa0 >> 2, as0 = (qa0 & 3) * 8;
    const int ar1 = (qa0 + 1) >> 2, as1 = ((qa0 + 1) & 3) * 8;
    const int br = tid >> 2, bs = (tid & 3) * 8;

    const int aTerm = (lane & 15) * LDA + (lane >> 4) * 8;
    const int bTerm = ((lane & 7) + ((lane >> 4) << 3)) * LDA + ((lane >> 3) & 1) * 8;
    const int aTileOff = (wm * 64) * LDA;
    const int bTileOff = (wn * 32) * LDA;

    float acc[4][4][4];
#pragma unroll
    for (int i = 0; i < 4; i++)
#pragma unroll
        for (int j = 0; j < 4; j++)
#pragma unroll
            for (int k = 0; k < 4; k++) acc[i][j][k] = 0.f;

    auto load_stage = [&](int kt, int s) {
        const int k0 = kt * 32;
        const uint32_t sbase = sb + (uint32_t)(s * ST_TOTAL) * 2;
        {
            int r0a = row0 + ar0, r1a = row0 + ar1;
            int sz0 = (r0a < N_NODES) ? 16 : 0;
            int sz1 = (r1a < N_NODES) ? 16 : 0;
            size_t o0 = (size_t)min(r0a, N_NODES - 1) * DHID + k0 + as0;
            size_t o1 = (size_t)min(r1a, N_NODES - 1) * DHID + k0 + as1;
            cpa16(sbase + (ar0 * LDA + as0) * 2, Ah + o0, sz0);
            cpa16(sbase + (ar1 * LDA + as1) * 2, Ah + o1, sz1);
        }
        {
            size_t ob = (size_t)(col0 + br) * DHID + k0 + bs;
            cpa16(sbase + (OFF_BH + br * LDA + bs) * 2, Bh + ob, 16);
        }
        asm volatile("cp.async.commit_group;");
    };

    load_stage(0, 0);
    load_stage(1, 1);

    for (int kt = 0; kt < 8; kt++) {
        const int s = kt % 3;
        if (kt < 7) asm volatile("cp.async.wait_group 1;");
        else        asm volatile("cp.async.wait_group 0;");
        __syncthreads();
        if (kt < 6) load_stage(kt + 2, (kt + 2) % 3);

        const uint32_t stg = sb + (uint32_t)(s * ST_TOTAL) * 2;
        const uint32_t aBase = stg + (uint32_t)(aTerm + aTileOff) * 2;
        const uint32_t bBase = stg + (uint32_t)(OFF_BH + bTerm + bTileOff) * 2;

#pragma unroll
        for (int kk = 0; kk < 32; kk += 16) {
            uint32_t ah[4][4], bh[4][2];
#pragma unroll
            for (int mt = 0; mt < 4; mt++) {
                uint32_t off = (uint32_t)(mt * 16 * LDA + kk) * 2;
                ldsm4(ah[mt], aBase + off);
            }
#pragma unroll
            for (int p = 0; p < 2; p++) {
                uint32_t off = (uint32_t)(p * 16 * LDA + kk) * 2;
                uint32_t t[4];
                ldsm4(t, bBase + off);
                bh[2 * p][0] = t[0]; bh[2 * p][1] = t[1];
                bh[2 * p + 1][0] = t[2]; bh[2 * p + 1][1] = t[3];
            }
#pragma unroll
            for (int mt = 0; mt < 4; mt++)
#pragma unroll
                for (int nt = 0; nt < 4; nt++)
                    mma_f16(acc[mt][nt], ah[mt], bh[nt]);
        }
    }

#pragma unroll
    for (int mt = 0; mt < 4; mt++) {
        int r0 = row0 + wm * 64 + mt * 16 + g;
#pragma unroll
        for (int half = 0; half < 2; half++) {
            int row = r0 + half * 8;
            if (row >= N_NODES) continue;
#pragma unroll
            for (int nt = 0; nt < 4; nt++) {
                int col = col0 + wn * 32 + nt * 8 + tg * 2;
                float c0 = acc[mt][nt][half * 2 + 0];
                float c1 = acc[mt][nt][half * 2 + 1];
                if (MODE == 0) {
                    c0 = fmaxf(c0 + __ldg(bias + col), 0.f);
                    c1 = fmaxf(c1 + __ldg(bias + col + 1), 0.f);
                    *reinterpret_cast<uint32_t*>(Ch + (size_t)row * DHID + col) = pack_f16(c0, c1);
                } else {
                    if (col0 == 0) {
                        *reinterpret_cast<uint32_t*>(Ch + (size_t)row * DIN + col) = pack_f16(c0, c1);
                    } else {
                        *reinterpret_cast<float2*>(Cq + (size_t)row * DIN + (col - 128)) =
                            make_float2(c0, c1);
                    }
                }
            }
        }
    }
}

// ---------------------------------------------------------------------------
extern "C" void kernel_launch(void* const* d_in, const int* in_sizes, int n_in,
                              void* d_out, int out_size) {
    const float* x   = (const float*)d_in[0];
    const int*   ei  = (const int*)d_in[1];
    const float* W1l = (const float*)d_in[2];
    const float* b1  = (const float*)d_in[3];
    const float* W1r = (const float*)d_in[4];
    const float* W2l = (const float*)d_in[5];
    const float* b2  = (const float*)d_in[6];
    const float* W2r = (const float*)d_in[7];
    float* out = (float*)d_out;

    const int E = in_sizes[1] / 2;
    const int* src = ei;
    const int* dst = ei + E;

    int *degi, *off, *cur, *esrc, *psum;
    float *q;
    uint16_t *x16, *a1, *h16, *p16, *wh;
    cudaGetSymbolAddress((void**)&degi, g_degi);
    cudaGetSymbolAddress((void**)&off,  g_off);
    cudaGetSymbolAddress((void**)&cur,  g_cur);
    cudaGetSymbolAddress((void**)&esrc, g_esrc);
    cudaGetSymbolAddress((void**)&psum, g_psum);
    cudaGetSymbolAddress((void**)&x16,  g_x16);
    cudaGetSymbolAddress((void**)&a1,   g_a1);
    cudaGetSymbolAddress((void**)&h16,  g_h16);
    cudaGetSymbolAddress((void**)&p16,  g_p16);
    cudaGetSymbolAddress((void**)&q,    g_q);
    cudaGetSymbolAddress((void**)&wh,   g_wh);

    const int SMEM = 3 * ST_TOTAL * 2;   // 92160 B
    static cudaStream_t s1 = nullptr;
    static cudaEvent_t evF, evJ;
    if (!s1) {
        cudaFuncSetAttribute(gemm_mma<0>, cudaFuncAttributeMaxDynamicSharedMemorySize, SMEM);
        cudaFuncSetAttribute(gemm_mma<1>, cudaFuncAttributeMaxDynamicSharedMemorySize, SMEM);
        cudaStreamCreateWithFlags(&s1, cudaStreamNonBlocking);
        cudaEventCreateWithFlags(&evF, cudaEventDisableTiming);
        cudaEventCreateWithFlags(&evJ, cudaEventDisableTiming);
    }

    const dim3 GG((N_NODES + 255) / 256, 2);
    const int AGG_GRID = (N_NODES + 7) / 8;

    // ---- fork: side stream runs the fused converts ----
    cudaEventRecord(evF, 0);
    cudaStreamWaitEvent(s1, evF, 0);
    conv_kernel<<<(N_NODES * DIN / 4 + 255) / 256, 256, 0, s1>>>(
        x, x16, W1l, W1r, W2l, W2r, wh);

    // ---- main stream: CSR build (scan2 fused into scan3) ----
    zero_int_kernel<<<(N_NODES + 255) / 256, 256>>>(degi, N_NODES);
    degi_kernel<<<(E + 255) / 256, 256>>>(dst, E, degi);
    scan1_kernel<<<SCAN_NB, 256>>>(degi, psum);
    scan3_kernel<<<SCAN_NB, 256>>>(degi, psum, off, cur, E);
    fill_kernel<<<((E + 1) / 2 + 255) / 256, 256>>>(src, dst, off, cur, esrc, E);

    // ---- join converts before layer 1 ----
    cudaEventRecord(evJ, s1);
    cudaStreamWaitEvent(0, evJ, 0);

    // layer 1
    agg_csr_kernel<0><<<AGG_GRID, 256>>>(x16, off, esrc, a1, nullptr, nullptr, nullptr);
    gemm_mma<0><<<GG, 512, SMEM>>>(a1, wh, b1, h16, nullptr);

    // layer 2
    gemm_mma<1><<<GG, 512, SMEM>>>(h16, wh + DHID * DHID, nullptr, p16, q);
    agg_csr_kernel<1><<<AGG_GRID, 256>>>(p16, off, esrc, nullptr, q, b2, out);
}